// round 16
// baseline (speedup 1.0000x reference)
#include <cuda_runtime.h>
#include <cuda_bf16.h>

#define FULL 0xffffffffu
#define L2E  1.4426950408889634f
#define LN2  0.6931471805599453f
#define CRF_S 1024
#define CRF_T 16
#define ONEBF 0x3F803F80u

static __device__ __forceinline__ float ex2f_(float x){ float y; asm("ex2.approx.ftz.f32 %0,%1;" :"=f"(y):"f"(x)); return y; }
static __device__ __forceinline__ float lg2f_(float x){ float y; asm("lg2.approx.ftz.f32 %0,%1;" :"=f"(y):"f"(x)); return y; }

union UBF { unsigned u; __nv_bfloat162 b; float f; };
static __device__ __forceinline__ unsigned bf2u(__nv_bfloat162 v){ UBF c; c.b = v; return c.u; }
static __device__ __forceinline__ __nv_bfloat162 u2bf(unsigned u){ UBF c; c.u = u; return c.b; }
static __device__ __forceinline__ float bflo_f(unsigned u){ UBF c; c.u = u << 16; return c.f; }
static __device__ __forceinline__ float bfhi_f(unsigned u){ UBF c; c.u = u & 0xffff0000u; return c.f; }

#define DLO(x) __low2bfloat162(u2bf(x))
#define DHI(x) __high2bfloat162(u2bf(x))

__device__ float g_nll[1024];

// 16x2 FMA tree from 8 packed regs against an Ep array
#define TREE(SS, EP, OUT) \
    __nv_bfloat162 OUT##A = __hmul2(DLO(SS##0), EP[0]); \
    __nv_bfloat162 OUT##B = __hmul2(DHI(SS##0), EP[1]); \
    __nv_bfloat162 OUT##C = __hmul2(DLO(SS##1), EP[2]); \
    __nv_bfloat162 OUT##D = __hmul2(DHI(SS##1), EP[3]); \
    OUT##A = __hfma2(DLO(SS##2), EP[ 4], OUT##A); \
    OUT##B = __hfma2(DHI(SS##2), EP[ 5], OUT##B); \
    OUT##C = __hfma2(DLO(SS##3), EP[ 6], OUT##C); \
    OUT##D = __hfma2(DHI(SS##3), EP[ 7], OUT##D); \
    OUT##A = __hfma2(DLO(SS##4), EP[ 8], OUT##A); \
    OUT##B = __hfma2(DHI(SS##4), EP[ 9], OUT##B); \
    OUT##C = __hfma2(DLO(SS##5), EP[10], OUT##C); \
    OUT##D = __hfma2(DHI(SS##5), EP[11], OUT##D); \
    OUT##A = __hfma2(DLO(SS##6), EP[12], OUT##A); \
    OUT##B = __hfma2(DHI(SS##6), EP[13], OUT##B); \
    OUT##C = __hfma2(DLO(SS##7), EP[14], OUT##C); \
    OUT##D = __hfma2(DHI(SS##7), EP[15], OUT##D); \
    OUT##A = __hadd2(OUT##A, OUT##B); OUT##C = __hadd2(OUT##C, OUT##D); \
    OUT##A = __hadd2(OUT##A, OUT##C);

// shared gather core for one round: store both chains' v, one sync, load both
#define ROUND_CORE(K) \
    unsigned vF_ = bf2u(__hmul2(u2bf(pkF), u2bf(gpkF[(K)]))); \
    unsigned vB_ = bf2u(__hmul2(u2bf(pkB), u2bf(gpkB[(K)]))); \
    asm volatile("st.shared.b32 [%0], %1;" :: "r"(smwF + (((K)&1)<<9)), "r"(vF_) : "memory"); \
    asm volatile("st.shared.b32 [%0], %1;" :: "r"(smwB + (((K)&1)<<9)), "r"(vB_) : "memory"); \
    __syncwarp(); \
    unsigned f0,f1,f2,f3,f4,f5,f6,f7,b0,b1,b2,b3,b4,b5,b6,b7; \
    asm volatile("ld.shared.v4.b32 {%0,%1,%2,%3}, [%4];" \
        : "=r"(f0),"=r"(f1),"=r"(f2),"=r"(f3) : "r"(smrF + (((K)&1)<<9)) : "memory"); \
    asm volatile("ld.shared.v4.b32 {%0,%1,%2,%3}, [%4];" \
        : "=r"(f4),"=r"(f5),"=r"(f6),"=r"(f7) : "r"(smrF + (((K)&1)<<9) + 16) : "memory"); \
    asm volatile("ld.shared.v4.b32 {%0,%1,%2,%3}, [%4];" \
        : "=r"(b0),"=r"(b1),"=r"(b2),"=r"(b3) : "r"(smrB + (((K)&1)<<9)) : "memory"); \
    asm volatile("ld.shared.v4.b32 {%0,%1,%2,%3}, [%4];" \
        : "=r"(b4),"=r"(b5),"=r"(b6),"=r"(b7) : "r"(smrB + (((K)&1)<<9) + 16) : "memory"); \
    TREE(f, EpF, RF); \
    TREE(b, EpB, RB);

// fast round (both chains unmasked)
#define ROUND_F(K) do { \
    ROUND_CORE(K); \
    ptF = vF_; pkF = bf2u(RFA); \
    ptB = vB_; pkB = bf2u(RBA); } while (0)

// fast round with off-chain renorm folded into gpk[K+1] (power-of-2, exact)
#define ROUND_FR(K) do { \
    ROUND_CORE(K); \
    ptF = vF_; pkF = bf2u(RFA); \
    ptB = vB_; pkB = bf2u(RBA); \
    int EbF_ = (int)((f0 >> 7) & 0xffu); \
    unsigned hF_ = ((unsigned)(254 - EbF_)) << 7; \
    gpkF[(K)+1] = bf2u(__hmul2(u2bf(gpkF[(K)+1]), u2bf(hF_ | (hF_ << 16)))); \
    offF += (float)(EbF_ - 127); \
    int EbB_ = (int)((b0 >> 7) & 0xffu); \
    unsigned hB_ = ((unsigned)(254 - EbB_)) << 7; \
    gpkB[(K)+1] = bf2u(__hmul2(u2bf(gpkB[(K)+1]), u2bf(hB_ | (hB_ << 16)))); \
    offB += (float)(EbB_ - 127); } while (0)

// explicit-state renorm (masked path)
#define RENORMX(PK, PT, OFF) do { \
    unsigned u0_ = __shfl_sync(FULL, PK, 0, 8); \
    int Eb_ = (int)((u0_ >> 7) & 0xffu); \
    unsigned h_ = ((unsigned)(254 - Eb_)) << 7; \
    unsigned scl_ = h_ | (h_ << 16); \
    PK = bf2u(__hmul2(u2bf(PK), u2bf(scl_))); \
    PT = bf2u(__hmul2(u2bf(PT), u2bf(scl_))); \
    OFF += (float)(Eb_ - 127); \
} while (0)

// masked round (gated commits per chain)
#define ROUND_S(K, GFREG, GFK, GBREG, GBK) do { \
    ROUND_CORE(K); \
    int gF_ = __shfl_sync(FULL, (GFREG), (GFK), 8); \
    int gB_ = __shfl_sync(FULL, (GBREG), (GBK), 8); \
    if (gF_) { ptF = vF_; pkF = bf2u(RFA); } \
    if (gB_) { ptB = vB_; pkB = bf2u(RBA); } \
    if (((K)&7)==7) { RENORMX(pkF, ptF, offF); RENORMX(pkB, ptB, offB); } } while (0)

__global__ void __launch_bounds__(64)
crf_forward_kernel(const float* __restrict__ em,
                   const int* __restrict__ tags,
                   const int* __restrict__ mask,
                   const float* __restrict__ trans,
                   const float* __restrict__ start_t,
                   const float* __restrict__ end_t)
{
    __shared__ float s_trans[256];
    __shared__ float s_start[16];
    __shared__ __align__(16) unsigned s_gb[2][16][8];  // [buf][slot*2+chain][lane]
    int tid = threadIdx.x;
    for (int i = tid; i < 256; i += 64) s_trans[i] = trans[i];
    if (tid < 16) s_start[tid] = start_t[tid];
    __syncthreads();

    const int lane = tid & 31;
    const int j8   = lane & 7;                       // lane within 8-lane group
    const int g    = lane >> 3;                      // group 0..3
    const int b    = blockIdx.x * 8 + (tid >> 5) * 4 + g;
    const int c0   = j8 * 2;                         // owned state pair

    const int slot = (tid >> 5) * 4 + g;             // 0..7
    const unsigned smwF = (unsigned)__cvta_generic_to_shared(&s_gb[0][slot*2    ][j8]);
    const unsigned smwB = (unsigned)__cvta_generic_to_shared(&s_gb[0][slot*2 + 1][j8]);
    const unsigned smrF = (unsigned)__cvta_generic_to_shared(&s_gb[0][slot*2    ][0]);
    const unsigned smrB = (unsigned)__cvta_generic_to_shared(&s_gb[0][slot*2 + 1][0]);

    const float* emb = em   + (size_t)b * CRF_S * CRF_T;
    const int*   tp  = tags + (size_t)b * CRF_S;
    const int*   mp  = mask + (size_t)b * CRF_S;
    const float* emL = emb + c0;

    // E operands: fwd = column pair, bwd = row pair
    __nv_bfloat162 EpF[16], EpB[16];
    #pragma unroll
    for (int i = 0; i < 16; i++) {
        EpF[i] = __floats2bfloat162_rn(ex2f_(__ldg(trans + i*16 + c0)     * L2E),
                                       ex2f_(__ldg(trans + i*16 + c0 + 1) * L2E));
        EpB[i] = __floats2bfloat162_rn(ex2f_(__ldg(trans + c0*16 + i)     * L2E),
                                       ex2f_(__ldg(trans + (c0+1)*16 + i) * L2E));
    }

    // ---- block-0 preloads, both chains ----
    float2 emF[16], emB[16];
    #pragma unroll
    for (int u = 0; u < 16; u++) {
        emF[u] = __ldg((const float2*)(emL + (size_t)u * 16));
        emB[u] = __ldg((const float2*)(emL + (size_t)(1023 - u) * 16));
    }
    int ftA_c = __ldg(tp + j8),        ftB_c = __ldg(tp + 8 + j8);
    int ftA_n = __ldg(tp + 16 + j8),   ftB_n = __ldg(tp + 24 + j8);
    int btA_c = __ldg(tp + 512 + j8),  btB_c = __ldg(tp + 520 + j8);
    int btA_n = __ldg(tp + 528 + j8),  btB_n = __ldg(tp + 536 + j8);
    int fmA_c = __ldg(mp + j8),        fmB_c = __ldg(mp + 8 + j8);
    int bmA_c = __ldg(mp + 512 + j8),  bmB_c = __ldg(mp + 520 + j8);
    int gF0_c = __ldg(mp + j8),        gF1_c = __ldg(mp + 8 + j8);
    int gB0_c = __ldg(mp + 1023 - j8), gB1_c = __ldg(mp + 1015 - j8);
    float feA_c = __ldg(emb + (size_t)(j8)*16       + ftA_c);
    float feB_c = __ldg(emb + (size_t)(8 + j8)*16   + ftB_c);
    float beA_c = __ldg(emb + (size_t)(512 + j8)*16 + btA_c);
    float beB_c = __ldg(emb + (size_t)(520 + j8)*16 + btB_c);

    unsigned pkF, ptF = ONEBF, pkB, ptB = ONEBF;
    float offF, offB = 0.0f, gold = 0.0f;
    int carryF = 0, carryB = __ldg(tp + 511);
    int packlm = -2147483647;

    // ---- init (uniform across warp) ----
    {
        float sA = (s_start[c0]   + emF[0].x) * L2E;
        float sB = (s_start[c0+1] + emF[0].y) * L2E;
        float m0 = __shfl_sync(FULL, sA, 0, 8);
        pkF  = bf2u(__floats2bfloat162_rn(ex2f_(sA - m0), ex2f_(sB - m0)));
        offF = m0;
        pkB  = bf2u(__floats2bfloat162_rn(ex2f_(__ldg(end_t + c0)   * L2E),
                                          ex2f_(__ldg(end_t + c0+1) * L2E)));
        if (j8 == 0) gF0_c = 1;                     // t=0 init ungated per reference
    }

    // ---- gpk for block 0 ----
    unsigned gpkF[16], gpkB[16];
    #pragma unroll
    for (int u = 0; u < 16; u++) {
        gpkF[u] = bf2u(__floats2bfloat162_rn(ex2f_(emF[u].x * L2E), ex2f_(emF[u].y * L2E)));
        gpkB[u] = bf2u(__floats2bfloat162_rn(ex2f_(emB[u].x * L2E), ex2f_(emB[u].y * L2E)));
    }
    gpkF[0] = ONEBF;                                 // em_0 folded into p0

    int ftA_nn = 0, ftB_nn = 0, btA_nn = 0, btB_nn = 0;
    int fmA_n, fmB_n, bmA_n, bmB_n, gF0_n, gF1_n, gB0_n, gB1_n;
    float feA_n, feB_n, beA_n, beB_n;

    for (int nb = 0; nb < 32; nb++) {
        const int k0 = nb * 16;

        // ---- prefetch next block, both chains ----
        if (nb < 31) {
            const int kn = k0 + 16;
            #pragma unroll
            for (int u = 0; u < 16; u++) {
                emF[u] = __ldg((const float2*)(emL + (size_t)(kn + u) * 16));
                emB[u] = __ldg((const float2*)(emL + (size_t)(1023 - kn - u) * 16));
            }
            fmA_n = __ldg(mp + kn + j8);        fmB_n = __ldg(mp + kn + 8 + j8);
            bmA_n = __ldg(mp + 512 + kn + j8);  bmB_n = __ldg(mp + 512 + kn + 8 + j8);
            gF0_n = __ldg(mp + kn + j8);        gF1_n = __ldg(mp + kn + 8 + j8);
            gB0_n = __ldg(mp + 1023 - kn - j8); gB1_n = __ldg(mp + 1015 - kn - j8);
            feA_n = __ldg(emb + (size_t)(kn + j8)*16           + ftA_n);
            feB_n = __ldg(emb + (size_t)(kn + 8 + j8)*16       + ftB_n);
            beA_n = __ldg(emb + (size_t)(512 + kn + j8)*16     + btA_n);
            beB_n = __ldg(emb + (size_t)(512 + kn + 8 + j8)*16 + btB_n);
            if (nb < 30) {
                ftA_nn = __ldg(tp + kn + 16 + j8);       ftB_nn = __ldg(tp + kn + 24 + j8);
                btA_nn = __ldg(tp + 512 + kn + 16 + j8); btB_nn = __ldg(tp + 512 + kn + 24 + j8);
            }
        }

        // ---- gold: 4 lane-local timesteps ----
        {
            int t  = k0 + j8;
            int tgp = __shfl_up_sync(FULL, ftA_c, 1, 8);
            int l7  = __shfl_sync(FULL, ftA_c, 7, 8);
            if (j8 == 0) tgp = carryF;
            carryF = l7;
            if (t == 0) {
                gold += s_start[ftA_c] + feA_c;
                if (fmA_c) packlm = ftA_c;
            } else if (fmA_c) {
                gold += feA_c + s_trans[ftA_c*16 + tgp];
                packlm = (t << 4) | ftA_c;
            }
            t   = k0 + 8 + j8;
            tgp = __shfl_up_sync(FULL, ftB_c, 1, 8);
            l7  = __shfl_sync(FULL, ftB_c, 7, 8);
            if (j8 == 0) tgp = carryF;
            carryF = l7;
            if (fmB_c) {
                gold += feB_c + s_trans[ftB_c*16 + tgp];
                packlm = (t << 4) | ftB_c;
            }
            t   = 512 + k0 + j8;
            tgp = __shfl_up_sync(FULL, btA_c, 1, 8);
            l7  = __shfl_sync(FULL, btA_c, 7, 8);
            if (j8 == 0) tgp = carryB;
            carryB = l7;
            if (bmA_c) {
                gold += beA_c + s_trans[btA_c*16 + tgp];
                packlm = (t << 4) | btA_c;
            }
            t   = 512 + k0 + 8 + j8;
            tgp = __shfl_up_sync(FULL, btB_c, 1, 8);
            l7  = __shfl_sync(FULL, btB_c, 7, 8);
            if (j8 == 0) tgp = carryB;
            carryB = l7;
            if (bmB_c) {
                gold += beB_c + s_trans[btB_c*16 + tgp];
                packlm = (t << 4) | btB_c;
            }
        }

        // ---- 16 rounds (one fwd + one bwd chain-step each) ----
        const unsigned bal = __ballot_sync(FULL,
            (gF0_c != 0) && (gF1_c != 0) && (gB0_c != 0) && (gB1_c != 0));
        if (bal == FULL) {
            ROUND_F(0);  ROUND_F(1);  ROUND_F(2);  ROUND_F(3);
            ROUND_F(4);  ROUND_F(5);  ROUND_FR(6); ROUND_F(7);
            ROUND_F(8);  ROUND_F(9);  ROUND_F(10); ROUND_F(11);
            ROUND_F(12); ROUND_F(13); ROUND_FR(14); ROUND_F(15);
        } else {
            ROUND_S(0,  gF0_c, 0, gB0_c, 0); ROUND_S(1,  gF0_c, 1, gB0_c, 1);
            ROUND_S(2,  gF0_c, 2, gB0_c, 2); ROUND_S(3,  gF0_c, 3, gB0_c, 3);
            ROUND_S(4,  gF0_c, 4, gB0_c, 4); ROUND_S(5,  gF0_c, 5, gB0_c, 5);
            ROUND_S(6,  gF0_c, 6, gB0_c, 6); ROUND_S(7,  gF0_c, 7, gB0_c, 7);
            ROUND_S(8,  gF1_c, 0, gB1_c, 0); ROUND_S(9,  gF1_c, 1, gB1_c, 1);
            ROUND_S(10, gF1_c, 2, gB1_c, 2); ROUND_S(11, gF1_c, 3, gB1_c, 3);
            ROUND_S(12, gF1_c, 4, gB1_c, 4); ROUND_S(13, gF1_c, 5, gB1_c, 5);
            ROUND_S(14, gF1_c, 6, gB1_c, 6); ROUND_S(15, gF1_c, 7, gB1_c, 7);
        }

        // ---- convert prefetched -> gpk; rotate pipelines ----
        if (nb < 31) {
            #pragma unroll
            for (int u = 0; u < 16; u++) {
                gpkF[u] = bf2u(__floats2bfloat162_rn(ex2f_(emF[u].x * L2E), ex2f_(emF[u].y * L2E)));
                gpkB[u] = bf2u(__floats2bfloat162_rn(ex2f_(emB[u].x * L2E), ex2f_(emB[u].y * L2E)));
            }
            ftA_c = ftA_n; ftB_c = ftB_n; ftA_n = ftA_nn; ftB_n = ftB_nn;
            btA_c = btA_n; btB_c = btB_n; btA_n = btA_nn; btB_n = btB_nn;
            fmA_c = fmA_n; fmB_c = fmB_n; bmA_c = bmA_n; bmB_c = bmB_n;
            gF0_c = gF0_n; gF1_c = gF1_n; gB0_c = gB0_n; gB1_c = gB1_n;
            feA_c = feA_n; feB_c = feB_n; beA_c = beA_n; beB_c = beB_n;
        }
    }

    // ---- epilogue: Z = sum_s alpha_511(s) * beta_511(s), in-lane ----
    float z = bflo_f(ptF)*bflo_f(pkB) + bfhi_f(ptF)*bfhi_f(pkB);
    z += __shfl_xor_sync(FULL, z, 4, 8);
    z += __shfl_xor_sync(FULL, z, 2, 8);
    z += __shfl_xor_sync(FULL, z, 1, 8);

    gold += __shfl_xor_sync(FULL, gold, 4, 8);
    gold += __shfl_xor_sync(FULL, gold, 2, 8);
    gold += __shfl_xor_sync(FULL, gold, 1, 8);

    packlm = max(packlm, __shfl_xor_sync(FULL, packlm, 4, 8));
    packlm = max(packlm, __shfl_xor_sync(FULL, packlm, 2, 8));
    packlm = max(packlm, __shfl_xor_sync(FULL, packlm, 1, 8));

    if (j8 == 0) {
        const int ltf = packlm & 15;
        const float logZ = (offF + offB + lg2f_(z)) * LN2;
        g_nll[b] = logZ - (gold + __ldg(end_t + ltf));
    }
}

__global__ void crf_reduce_kernel(float* __restrict__ out)
{
    __shared__ float sm[256];
    int tid = threadIdx.x;
    float v = g_nll[tid] + g_nll[tid + 256] + g_nll[tid + 512] + g_nll[tid + 768];
    sm[tid] = v;
    __syncthreads();
    #pragma unroll
    for (int s = 128; s > 0; s >>= 1) {
        if (tid < s) sm[tid] += sm[tid + s];
        __syncthreads();
    }
    if (tid == 0) out[0] = sm[0] * (1.0f / 1024.0f);
}

extern "C" void kernel_launch(void* const* d_in, const int* in_sizes, int n_in,
                              void* d_out, int out_size)
{
    const float* emissions = (const float*)d_in[0];
    const int*   tags      = (const int*)d_in[1];
    const int*   mask      = (const int*)d_in[2];
    const float* trans     = (const float*)d_in[3];
    const float* start_t   = (const float*)d_in[4];
    const float* end_t     = (const float*)d_in[5];
    float* out = (float*)d_out;

    crf_forward_kernel<<<128, 64>>>(emissions, tags, mask, trans, start_t, end_t);
    crf_reduce_kernel<<<1, 256>>>(out);
}

// round 17
// speedup vs baseline: 1.2704x; 1.2704x over previous
#include <cuda_runtime.h>
#include <cuda_bf16.h>

#define FULL 0xffffffffu
#define L2E  1.4426950408889634f
#define LN2  0.6931471805599453f

static __device__ __forceinline__ float ex2f_(float x){ float y; asm("ex2.approx.ftz.f32 %0,%1;" :"=f"(y):"f"(x)); return y; }
static __device__ __forceinline__ float lg2f_(float x){ float y; asm("lg2.approx.ftz.f32 %0,%1;" :"=f"(y):"f"(x)); return y; }

union UBF { unsigned u; __nv_bfloat162 b; float f; };
static __device__ __forceinline__ unsigned bf2u(__nv_bfloat162 v){ UBF c; c.b = v; return c.u; }
static __device__ __forceinline__ __nv_bfloat162 u2bf(unsigned u){ UBF c; c.u = u; return c.b; }
static __device__ __forceinline__ float bflo_f(unsigned u){ UBF c; c.u = u << 16; return c.f; }
static __device__ __forceinline__ float bfhi_f(unsigned u){ UBF c; c.u = u & 0xffff0000u; return c.f; }

#define MUL2(X,Y) bf2u(__hmul2(u2bf(X), u2bf(Y)))
// n = {lo=LO, hi=HI}  (cvt.bf16x2.f32 d,a,b -> d.hi=cvt(a), d.lo=cvt(b))
#define PACKBF(N, LO, HI) asm("cvt.rn.bf16x2.f32 %0, %1, %2;" : "=r"(N) : "f"(HI), "f"(LO))

#define MMA16816(D0,D1,D2,D3, A0,A1,A2,A3, B0,B1) \
    asm volatile("mma.sync.aligned.m16n8k16.row.col.f32.bf16.bf16.f32 " \
        "{%0,%1,%2,%3}, {%4,%5,%6,%7}, {%8,%9}, {%10,%11,%12,%13};" \
        : "=f"(D0),"=f"(D1),"=f"(D2),"=f"(D3) \
        : "r"(A0),"r"(A1),"r"(A2),"r"(A3), "r"(B0),"r"(B1), \
          "f"(0.0f),"f"(0.0f),"f"(0.0f),"f"(0.0f))

// scratch (device globals: no runtime allocation)
__device__ unsigned g_S[1024 * 32 * 128];   // per (b,chunk): 16x16 bf16 as 128 u32, row-major pairs
__device__ float    g_goldp[1024 * 32];
__device__ float    g_off2c[1024 * 32];
__device__ int      g_plm[1024 * 32];
__device__ float    g_nll[1024];

// f-pack build: n = (ex2(v.x*L2E), ex2(v.y*L2E))
#define BUILDF(N, V) do { float bx_ = ex2f_((V).x * L2E); float by_ = ex2f_((V).y * L2E); PACKBF(N, bx_, by_); } while (0)

// one matrix step: S <- (S * E) * diag(f_t)   [S kept as A-fragments a0..a3]
#define MSTEP(S) do { \
    unsigned flo_ = __shfl_sync(FULL, fwlo, ((S)<<2) | q); \
    unsigned fhi_ = __shfl_sync(FULL, fwhi, ((S)<<2) | q); \
    float d0,d1,d2,d3,d4,d5,d6,d7; \
    MMA16816(d0,d1,d2,d3, a0,a1,a2,a3, e10,e11); \
    MMA16816(d4,d5,d6,d7, a0,a1,a2,a3, e20,e21); \
    unsigned n0,n1,n2,n3; \
    PACKBF(n0,d0,d1); PACKBF(n1,d2,d3); PACKBF(n2,d4,d5); PACKBF(n3,d6,d7); \
    a0 = MUL2(n0,flo_); a1 = MUL2(n1,flo_); a2 = MUL2(n2,fhi_); a3 = MUL2(n3,fhi_); \
} while (0)

#define MSTEP_G(W,S) do { \
    unsigned flo_ = __shfl_sync(FULL, fwlo, ((S)<<2) | q); \
    unsigned fhi_ = __shfl_sync(FULL, fwhi, ((S)<<2) | q); \
    int gt_ = __shfl_sync(FULL, gatereg, (W)*8 + (S)); \
    float d0,d1,d2,d3,d4,d5,d6,d7; \
    MMA16816(d0,d1,d2,d3, a0,a1,a2,a3, e10,e11); \
    MMA16816(d4,d5,d6,d7, a0,a1,a2,a3, e20,e21); \
    unsigned n0,n1,n2,n3; \
    PACKBF(n0,d0,d1); PACKBF(n1,d2,d3); PACKBF(n2,d4,d5); PACKBF(n3,d6,d7); \
    if (gt_) { a0 = MUL2(n0,flo_); a1 = MUL2(n1,flo_); a2 = MUL2(n2,fhi_); a3 = MUL2(n3,fhi_); } \
} while (0)

// fast window: 8 steps; renorm folded into ONE step of next window's f-packs
#define WINDOW_F(W) do { \
    float2 elo_n, ehi_n; \
    if ((W) < 3) { \
        elo_n = __ldg((const float2*)(emb + (size_t)(base + ((W)+1)*8 + sw)*16 + 2*q)); \
        ehi_n = __ldg((const float2*)(emb + (size_t)(base + ((W)+1)*8 + sw)*16 + 2*q + 8)); \
    } \
    MSTEP(0); MSTEP(1); MSTEP(2); MSTEP(3); MSTEP(4); MSTEP(5); MSTEP(6); MSTEP(7); \
    if ((W) < 3) { \
        unsigned ua_ = __shfl_sync(FULL, a0, 0); \
        int e_ = (int)((ua_ >> 7) & 0xffu); \
        unsigned h_ = ((unsigned)(254 - e_)) << 7; \
        unsigned sclp_ = h_ | (h_ << 16); \
        off2 += (float)(e_ - 127); \
        BUILDF(fwlo, elo_n); BUILDF(fwhi, ehi_n); \
        if (sw == 0) { fwlo = MUL2(fwlo, sclp_); fwhi = MUL2(fwhi, sclp_); } \
    } \
} while (0)

// gated window: 8 gated steps; explicit in-place renorm (safe under masks)
#define WINDOW_G(W) do { \
    float2 elo_n, ehi_n; \
    if ((W) < 3) { \
        elo_n = __ldg((const float2*)(emb + (size_t)(base + ((W)+1)*8 + sw)*16 + 2*q)); \
        ehi_n = __ldg((const float2*)(emb + (size_t)(base + ((W)+1)*8 + sw)*16 + 2*q + 8)); \
    } \
    MSTEP_G(W,0); MSTEP_G(W,1); MSTEP_G(W,2); MSTEP_G(W,3); \
    MSTEP_G(W,4); MSTEP_G(W,5); MSTEP_G(W,6); MSTEP_G(W,7); \
    { unsigned ua_ = __shfl_sync(FULL, a0, 0); \
      int e_ = (int)((ua_ >> 7) & 0xffu); \
      unsigned h_ = ((unsigned)(254 - e_)) << 7; \
      unsigned sc_ = h_ | (h_ << 16); \
      a0 = MUL2(a0,sc_); a1 = MUL2(a1,sc_); a2 = MUL2(a2,sc_); a3 = MUL2(a3,sc_); \
      off2 += (float)(e_ - 127); } \
    if ((W) < 3) { BUILDF(fwlo, elo_n); BUILDF(fwhi, ehi_n); } \
} while (0)

__global__ void __launch_bounds__(128)
crf_chunk_kernel(const float* __restrict__ em,
                 const int* __restrict__ tags,
                 const int* __restrict__ mask,
                 const float* __restrict__ trans,
                 const float* __restrict__ start_t,
                 const float* __restrict__ end_t)
{
    __shared__ float s_trans[256];
    __shared__ float s_start[16];
    int tid = threadIdx.x;
    for (int i = tid; i < 256; i += 128) s_trans[i] = trans[i];
    if (tid < 16) s_start[tid] = start_t[tid];
    __syncthreads();

    const int lane = tid & 31;
    const int wg   = blockIdx.x * 4 + (tid >> 5);   // global warp id == b*32 + c
    const int b    = wg >> 5;
    const int c    = wg & 31;
    const int q    = lane & 3;        // thread-in-group (fragment col-pair index)
    const int g    = lane >> 2;       // fragment row/col group index
    const int sw   = lane >> 2;       // step-in-window this lane's f covers
    const int base = c * 32;

    const float* emb = em   + (size_t)b * 16384;
    const int*   tp  = tags + (size_t)b * 1024;
    const int*   mp  = mask + (size_t)b * 1024;

    // E fragments (B operand, col-major k16n8): E[k][n] = exp(trans[k][n])
    unsigned e10, e11, e20, e21;
    {
        float x0 = ex2f_(s_trans[(2*q  )*16 + g] * L2E);
        float x1 = ex2f_(s_trans[(2*q+1)*16 + g] * L2E);
        PACKBF(e10, x0, x1);
        x0 = ex2f_(s_trans[(2*q+8)*16 + g] * L2E);
        x1 = ex2f_(s_trans[(2*q+9)*16 + g] * L2E);
        PACKBF(e11, x0, x1);
        x0 = ex2f_(s_trans[(2*q  )*16 + g + 8] * L2E);
        x1 = ex2f_(s_trans[(2*q+1)*16 + g + 8] * L2E);
        PACKBF(e20, x0, x1);
        x0 = ex2f_(s_trans[(2*q+8)*16 + g + 8] * L2E);
        x1 = ex2f_(s_trans[(2*q+9)*16 + g + 8] * L2E);
        PACKBF(e21, x0, x1);
    }

    // ---- gold path: one timestep per lane ----
    const int t_g = base + lane;
    const int mk  = __ldg(mp + t_g);
    {
        const int tg = __ldg(tp + t_g);
        const float emg = __ldg(emb + (size_t)t_g*16 + tg);
        float gd = 0.0f; int plm = -2147483647 - 1;
        if (t_g == 0) {
            gd = s_start[tg] + emg;
            if (mk) plm = tg;
        } else if (mk) {
            const int tgp = __ldg(tp + t_g - 1);
            gd = emg + s_trans[tg*16 + tgp];
            plm = (t_g << 4) | tg;
        }
        #pragma unroll
        for (int o = 16; o; o >>= 1) {
            gd  += __shfl_xor_sync(FULL, gd, o);
            plm  = max(plm, __shfl_xor_sync(FULL, plm, o));
        }
        if (lane == 0) { g_goldp[wg] = gd; g_plm[wg] = plm; }
    }

    // gate register: lane holds gate for t = base+lane; t=0 is not a recurrence step
    int gatereg = mk;
    if (c == 0 && lane == 0) gatereg = 0;
    const bool fast = (__ballot_sync(FULL, gatereg != 0) == FULL);

    // S = I as A-fragments (row-major m16k16)
    unsigned a0 = ((g == 2*q) ? 0x3F80u : 0u) | ((g == 2*q+1) ? 0x3F800000u : 0u);
    unsigned a3 = a0, a1 = 0u, a2 = 0u;
    float off2 = 0.0f;

    // window 0 f-packs
    unsigned fwlo, fwhi;
    {
        float2 elo = __ldg((const float2*)(emb + (size_t)(base + sw)*16 + 2*q));
        float2 ehi = __ldg((const float2*)(emb + (size_t)(base + sw)*16 + 2*q + 8));
        BUILDF(fwlo, elo); BUILDF(fwhi, ehi);
    }

    if (fast) {
        WINDOW_F(0); WINDOW_F(1); WINDOW_F(2); WINDOW_F(3);
        // final explicit renorm
        unsigned ua_ = __shfl_sync(FULL, a0, 0);
        int e_ = (int)((ua_ >> 7) & 0xffu);
        unsigned h_ = ((unsigned)(254 - e_)) << 7;
        unsigned sc_ = h_ | (h_ << 16);
        a0 = MUL2(a0,sc_); a1 = MUL2(a1,sc_); a2 = MUL2(a2,sc_); a3 = MUL2(a3,sc_);
        off2 += (float)(e_ - 127);
    } else {
        WINDOW_G(0); WINDOW_G(1); WINDOW_G(2); WINDOW_G(3);
    }

    // store S (row-major u32 pairs: word[r*8 + wi] = cols 2wi,2wi+1 of row r)
    unsigned* Sb = g_S + (size_t)wg * 128;
    Sb[g*8 + q]           = a0;
    Sb[(g + 8)*8 + q]     = a1;
    Sb[g*8 + q + 4]       = a2;
    Sb[(g + 8)*8 + q + 4] = a3;
    if (lane == 0) g_off2c[wg] = off2;
}

__global__ void __launch_bounds__(128)
crf_combine_kernel(const float* __restrict__ em,
                   const float* __restrict__ start_t,
                   const float* __restrict__ end_t)
{
    const int tid  = threadIdx.x;
    const int lane = tid & 31;
    const int j    = lane & 15;                    // state index
    const int b    = blockIdx.x * 8 + (tid >> 4);  // 2 batches per warp (width-16 groups)

    const float* emb = em + (size_t)b * 16384;

    // p0 = exp(start + em0), normalized to state 0
    float sA = (start_t[j] + __ldg(emb + j)) * L2E;
    float m0 = __shfl_sync(FULL, sA, 0, 16);
    float p  = ex2f_(sA - m0);
    float offA = m0;

    const unsigned* Sb = g_S + (size_t)b * 32 * 128;

    // prefetch chunk 0 column words
    unsigned wv[16];
    #pragma unroll
    for (int i = 0; i < 16; i++) wv[i] = __ldg(Sb + i*8 + (j >> 1));

    for (int cc = 0; cc < 32; cc++) {
        unsigned wn[16];
        if (cc < 31) {
            const unsigned* Sn = Sb + (size_t)(cc + 1) * 128;
            #pragma unroll
            for (int i = 0; i < 16; i++) wn[i] = __ldg(Sn + i*8 + (j >> 1));
        }
        // p_new[j] = sum_i p[i] * S[i][j]
        float acc = 0.0f;
        #pragma unroll
        for (int i = 0; i < 16; i++) {
            float qi = __shfl_sync(FULL, p, i, 16);
            float sv = (j & 1) ? bfhi_f(wv[i]) : bflo_f(wv[i]);
            acc = fmaf(qi, sv, acc);
        }
        // renorm (power of 2, exact)
        float r0 = __shfl_sync(FULL, acc, 0, 16);
        int e = (int)((__float_as_uint(r0) >> 23) & 0xffu);
        p = acc * __uint_as_float(((unsigned)(254 - e)) << 23);
        offA += (float)(e - 127);
        #pragma unroll
        for (int i = 0; i < 16; i++) wv[i] = wn[i];
    }

    // Z = sum_j p[j] * exp(end[j])
    float z = p * ex2f_(__ldg(end_t + j) * L2E);
    z += __shfl_xor_sync(FULL, z, 8, 16);
    z += __shfl_xor_sync(FULL, z, 4, 16);
    z += __shfl_xor_sync(FULL, z, 2, 16);
    z += __shfl_xor_sync(FULL, z, 1, 16);

    // per-batch scalars: each lane covers 2 chunks
    float gd = g_goldp[b*32 + j] + g_goldp[b*32 + j + 16];
    float o2 = g_off2c[b*32 + j] + g_off2c[b*32 + j + 16];
    int   pl = max(g_plm[b*32 + j], g_plm[b*32 + j + 16]);
    #pragma unroll
    for (int o = 8; o; o >>= 1) {
        gd += __shfl_xor_sync(FULL, gd, o, 16);
        o2 += __shfl_xor_sync(FULL, o2, o, 16);
        pl  = max(pl, __shfl_xor_sync(FULL, pl, o, 16));
    }

    if (j == 0) {
        const int ltf = pl & 15;
        const float logZ = (offA + o2 + lg2f_(z)) * LN2;
        g_nll[b] = logZ - (gd + __ldg(end_t + ltf));
    }
}

__global__ void crf_reduce_kernel(float* __restrict__ out)
{
    __shared__ float sm[256];
    int tid = threadIdx.x;
    float v = g_nll[tid] + g_nll[tid + 256] + g_nll[tid + 512] + g_nll[tid + 768];
    sm[tid] = v;
    __syncthreads();
    #pragma unroll
    for (int s = 128; s > 0; s >>= 1) {
        if (tid < s) sm[tid] += sm[tid + s];
        __syncthreads();
    }
    if (tid == 0) out[0] = sm[0] * (1.0f / 1024.0f);
}

extern "C" void kernel_launch(void* const* d_in, const int* in_sizes, int n_in,
                              void* d_out, int out_size)
{
    const float* emissions = (const float*)d_in[0];
    const int*   tags      = (const int*)d_in[1];
    const int*   mask      = (const int*)d_in[2];
    const float* trans     = (const float*)d_in[3];
    const float* start_t   = (const float*)d_in[4];
    const float* end_t     = (const float*)d_in[5];
    float* out = (float*)d_out;

    crf_chunk_kernel<<<8192, 128>>>(emissions, tags, mask, trans, start_t, end_t);
    crf_combine_kernel<<<128, 128>>>(emissions, start_t, end_t);
    crf_reduce_kernel<<<1, 256>>>(out);
}